// round 6
// baseline (speedup 1.0000x reference)
#include <cuda_runtime.h>
#include <cstdint>

#define N_NODES 30000
#define E_EDGES 480000
#define HID 256
#define HEADS 8
#define OUTC 32
#define L_LAYERS 6
#define NODE_IN 13
#define EDGE_IN 10
#define TILE 24

// ------------------- static device scratch -------------------
__device__ float g_h[N_NODES * HID];
__device__ float g_xl[N_NODES * HID];
__device__ float g_xr[N_NODES * HID];
__device__ float g_attrS[E_EDGES * EDGE_IN];   // permuted edge_attr (sorted edge order)
__device__ float g_h2[N_NODES * (HID / 2)];
__device__ float g_M[2][EDGE_IN * HID];        // composed attr->ea maps (ping-pong)
__device__ float g_cc[2][HID];
__device__ float g_P[L_LAYERS][EDGE_IN * HID]; // composed attr->ep maps
__device__ float g_q[L_LAYERS][HID];
__device__ int g_rowptr[N_NODES + 1];
__device__ int g_fill[N_NODES];
__device__ int g_perm[E_EDGES];
__device__ int g_src[E_EDGES];

static inline int cdiv(int a, int b) { return (a + b - 1) / b; }

// ------------------- CSR build -------------------
__global__ void k_zero_fill() {
    int i = blockIdx.x * blockDim.x + threadIdx.x;
    if (i < N_NODES) g_fill[i] = 0;
}

__global__ void k_count(const int* __restrict__ dst) {
    int e = blockIdx.x * blockDim.x + threadIdx.x;
    if (e < E_EDGES) atomicAdd(&g_fill[dst[e]], 1);
}

__global__ void k_scan() {  // single block, 1024 threads
    __shared__ int sh[1024];
    __shared__ int carry;
    int t = threadIdx.x;
    if (t == 0) carry = 0;
    __syncthreads();
    for (int base = 0; base < N_NODES; base += 1024) {
        int cbase = carry;
        int i = base + t;
        int v = (i < N_NODES) ? g_fill[i] : 0;
        sh[t] = v;
        __syncthreads();
        for (int off = 1; off < 1024; off <<= 1) {
            int tmp = (t >= off) ? sh[t - off] : 0;
            __syncthreads();
            sh[t] += tmp;
            __syncthreads();
        }
        if (i < N_NODES) {
            int ex = cbase + sh[t] - v;
            g_rowptr[i] = ex;
            g_fill[i] = ex;
        }
        __syncthreads();
        if (t == 0) carry = cbase + sh[1023];
        __syncthreads();
    }
    if (t == 0) g_rowptr[N_NODES] = carry;
}

__global__ void k_scatter(const int* __restrict__ src, const int* __restrict__ dst) {
    int e = blockIdx.x * blockDim.x + threadIdx.x;
    if (e < E_EDGES) {
        int d = dst[e];
        int pos = atomicAdd(&g_fill[d], 1);
        g_perm[pos] = e;
        g_src[pos] = src[e];
    }
}

__global__ void k_permattr(const float* __restrict__ eattr) {
    int i = blockIdx.x * blockDim.x + threadIdx.x;
    if (i < E_EDGES * EDGE_IN) {
        int e = i / EDGE_IN, j = i - e * EDGE_IN;
        g_attrS[i] = eattr[(size_t)g_perm[e] * EDGE_IN + j];
    }
}

// ------------------- node input projection -------------------
__global__ void k_hinit(const float* __restrict__ x, const float* __restrict__ W,
                        const float* __restrict__ b) {
    int n = blockIdx.x;
    int c = threadIdx.x;
    __shared__ float xr_[NODE_IN];
    if (c < NODE_IN) xr_[c] = x[n * NODE_IN + c];
    __syncthreads();
    float a = b[c];
#pragma unroll
    for (int k = 0; k < NODE_IN; k++) a += xr_[k] * W[k * HID + c];
    g_h[(size_t)n * HID + c] = a;
}

// ------------------- linear edge-chain composition (fp32 exact) -------------------
__global__ void k_initM(const float* __restrict__ edge_W, const float* __restrict__ edge_b) {
    int c = threadIdx.x;
#pragma unroll
    for (int r = 0; r < EDGE_IN; r++) g_M[0][r * HID + c] = edge_W[r * HID + c];
    g_cc[0][c] = edge_b[c];
}

// computes P_i = M@We, q_i = c@We; and (if doNext) M' = M@Weu, c' = c@Weu + beu
__global__ void k_compose(const float* __restrict__ We, const float* __restrict__ Weu,
                          const float* __restrict__ beu, int layer, int cur, int doNext) {
    int c = threadIdx.x;  // 256
    __shared__ float sM[EDGE_IN * HID];
    __shared__ float sc[HID];
    for (int t = c; t < EDGE_IN * HID; t += HID) sM[t] = g_M[cur][t];
    sc[c] = g_cc[cur][c];
    __syncthreads();
    float accP[EDGE_IN], accM[EDGE_IN];
    float accq = 0.f, accc = 0.f;
#pragma unroll
    for (int r = 0; r < EDGE_IN; r++) { accP[r] = 0.f; accM[r] = 0.f; }
    for (int k = 0; k < HID; k++) {
        float we = We[k * HID + c];
        float wu = doNext ? Weu[k * HID + c] : 0.f;
        float ck = sc[k];
        accq += ck * we;
        accc += ck * wu;
#pragma unroll
        for (int r = 0; r < EDGE_IN; r++) {
            float m = sM[r * HID + k];
            accP[r] += m * we;
            accM[r] += m * wu;
        }
    }
#pragma unroll
    for (int r = 0; r < EDGE_IN; r++) g_P[layer][r * HID + c] = accP[r];
    g_q[layer][c] = accq;
    if (doNext) {
#pragma unroll
        for (int r = 0; r < EDGE_IN; r++) g_M[1 - cur][r * HID + c] = accM[r];
        g_cc[1 - cur][c] = accc + beu[c];
    }
}

// ------------------- tf32 helpers -------------------
__device__ __forceinline__ uint32_t f2tf32(float x) {
    uint32_t r;
    asm("cvt.rna.tf32.f32 %0, %1;" : "=r"(r) : "f"(x));
    return r;
}

__device__ __forceinline__ void mma_tf32(float& c0, float& c1, float& c2, float& c3,
                                         uint32_t a0, uint32_t a1, uint32_t a2, uint32_t a3,
                                         uint32_t b0, uint32_t b1) {
    asm volatile(
        "mma.sync.aligned.m16n8k8.row.col.f32.tf32.tf32.f32 "
        "{%0,%1,%2,%3},{%4,%5,%6,%7},{%8,%9},{%0,%1,%2,%3};\n"
        : "+f"(c0), "+f"(c1), "+f"(c2), "+f"(c3)
        : "r"(a0), "r"(a1), "r"(a2), "r"(a3), "r"(b0), "r"(b1));
}

// ------------------- tensor-core GEMM, 128x128x32 tiles -------------------
__global__ __launch_bounds__(256, 2) void k_mma(const float* __restrict__ A,
                                                const float* __restrict__ B,
                                                const float* __restrict__ bias,
                                                float* __restrict__ C,
                                                int M, int N, int K, int act) {
    __shared__ uint32_t As[128][36];
    __shared__ uint32_t Bs[32][136];

    const int tid = threadIdx.x;
    const int lane = tid & 31;
    const int warp = tid >> 5;
    const int g = lane >> 2;
    const int t4 = lane & 3;
    const int wm = warp >> 1;
    const int wn = warp & 1;
    const int row0 = blockIdx.y * 128;
    const int col0 = blockIdx.x * 128;

    float acc[2][8][4];
#pragma unroll
    for (int mi = 0; mi < 2; mi++)
#pragma unroll
        for (int ni = 0; ni < 8; ni++)
#pragma unroll
            for (int c = 0; c < 4; c++) acc[mi][ni][c] = 0.f;

    for (int kt = 0; kt < K; kt += 32) {
#pragma unroll
        for (int v = 0; v < 4; v++) {
            int f = tid + v * 256;
            int row = f >> 3;
            int c4 = f & 7;
            int r = row0 + row;
            float4 av = make_float4(0.f, 0.f, 0.f, 0.f);
            if (r < M) av = *(const float4*)(A + (size_t)r * K + kt + c4 * 4);
            uint4 u;
            u.x = f2tf32(av.x); u.y = f2tf32(av.y); u.z = f2tf32(av.z); u.w = f2tf32(av.w);
            *(uint4*)&As[row][c4 * 4] = u;
        }
#pragma unroll
        for (int v = 0; v < 4; v++) {
            int f = tid + v * 256;
            int row = f >> 5;
            int c4 = f & 31;
            float4 bv = *(const float4*)(B + (size_t)(kt + row) * N + col0 + c4 * 4);
            uint4 u;
            u.x = f2tf32(bv.x); u.y = f2tf32(bv.y); u.z = f2tf32(bv.z); u.w = f2tf32(bv.w);
            *(uint4*)&Bs[row][c4 * 4] = u;
        }
        __syncthreads();

#pragma unroll
        for (int kk = 0; kk < 4; kk++) {
            int k0 = kk * 8;
            uint32_t a[2][4];
#pragma unroll
            for (int mi = 0; mi < 2; mi++) {
                int mrow = wm * 32 + mi * 16;
                a[mi][0] = As[mrow + g][k0 + t4];
                a[mi][1] = As[mrow + 8 + g][k0 + t4];
                a[mi][2] = As[mrow + g][k0 + t4 + 4];
                a[mi][3] = As[mrow + 8 + g][k0 + t4 + 4];
            }
            uint32_t b[8][2];
#pragma unroll
            for (int ni = 0; ni < 8; ni++) {
                int ncol = wn * 64 + ni * 8;
                b[ni][0] = Bs[k0 + t4][ncol + g];
                b[ni][1] = Bs[k0 + t4 + 4][ncol + g];
            }
#pragma unroll
            for (int mi = 0; mi < 2; mi++)
#pragma unroll
                for (int ni = 0; ni < 8; ni++)
                    mma_tf32(acc[mi][ni][0], acc[mi][ni][1], acc[mi][ni][2], acc[mi][ni][3],
                             a[mi][0], a[mi][1], a[mi][2], a[mi][3], b[ni][0], b[ni][1]);
        }
        __syncthreads();
    }

#pragma unroll
    for (int mi = 0; mi < 2; mi++) {
#pragma unroll
        for (int j = 0; j < 2; j++) {
            int r = row0 + wm * 32 + mi * 16 + j * 8 + g;
            if (r >= M) continue;
#pragma unroll
            for (int ni = 0; ni < 8; ni++) {
                int c = col0 + wn * 64 + ni * 8 + 2 * t4;
                float v0 = acc[mi][ni][j * 2 + 0];
                float v1 = acc[mi][ni][j * 2 + 1];
                if (bias) { v0 += bias[c]; v1 += bias[c + 1]; }
                if (act == 1) {
                    v0 = v0 >= 0.f ? v0 : 0.01f * v0;
                    v1 = v1 >= 0.f ? v1 : 0.01f * v1;
                }
                *(float2*)(C + (size_t)r * N + c) = make_float2(v0, v1);
            }
        }
    }
}

// ------------------- fused logits + online softmax + aggregation + BN ------------
// one block per destination node; xl[src] rows staged once in shared and reused
__global__ __launch_bounds__(256, 4) void k_fused(const float* __restrict__ P,
                                                  const float* __restrict__ q,
                                                  const float* __restrict__ att,
                                                  const float* __restrict__ conv_b,
                                                  const float* __restrict__ bn_g,
                                                  const float* __restrict__ bn_b,
                                                  const float* __restrict__ bn_rm,
                                                  const float* __restrict__ bn_rv,
                                                  int layer) {
    __shared__ float sP[EDGE_IN * HID];      // 10 KB
    __shared__ float sq[HID];                // 1 KB
    __shared__ float satt[HID];              // 1 KB
    __shared__ float sxr[HID];               // 1 KB
    __shared__ float sxl[TILE][HID];         // 24 KB
    __shared__ float slog[TILE * HEADS];
    __shared__ float sw[TILE * HEADS];
    __shared__ float sattr[TILE * EDGE_IN];
    __shared__ int ssrc[TILE];
    __shared__ float sm[HEADS], sden[HEADS], sscale[HEADS];

    const int n = blockIdx.x;
    const int t = threadIdx.x;
    const int lane = t & 31;
    const int wid = t >> 5;
    const int head = t >> 5;  // channel t belongs to head t/32

    // stage per-layer constants
    for (int i = t; i < EDGE_IN * HID; i += 256) sP[i] = P[i];
    sq[t] = q[t];
    satt[t] = att[t];
    sxr[t] = g_xr[(size_t)n * HID + t];
    if (t < HEADS) { sm[t] = -1e30f; sden[t] = 0.f; }

    float acc = 0.f;
    const int s0 = g_rowptr[n], s1 = g_rowptr[n + 1];

    for (int c0 = s0; c0 < s1; c0 += TILE) {
        int cnt = min(TILE, s1 - c0);
        __syncthreads();  // protects sxl/ssrc reuse + constants on first iter
        if (t < cnt) ssrc[t] = g_src[c0 + t];
        for (int i = t; i < cnt * EDGE_IN; i += 256)
            sattr[i] = g_attrS[(size_t)c0 * EDGE_IN + i];
        __syncthreads();
        // stage xl rows: 64 threads per row, 4 rows at a time (float4, coalesced)
        {
            int cj = t & 63;
            for (int r = t >> 6; r < cnt; r += 4) {
                float4 v = ((const float4*)(g_xl + (size_t)ssrc[r] * HID))[cj];
                ((float4*)sxl[r])[cj] = v;
            }
        }
        __syncthreads();
        // logits: warp w handles edges w, w+8, ...
        for (int e = wid; e < cnt; e += 8) {
            float lg[HEADS];
#pragma unroll
            for (int h = 0; h < HEADS; h++) {
                int c = h * 32 + lane;
                float ep = sq[c];
#pragma unroll
                for (int k = 0; k < EDGE_IN; k++)
                    ep = fmaf(sattr[e * EDGE_IN + k], sP[k * HID + c], ep);
                float m = sxl[e][c] + sxr[c] + ep;
                m = m >= 0.f ? m : 0.2f * m;
                lg[h] = m * satt[c];
            }
#pragma unroll
            for (int h = 0; h < HEADS; h++)
#pragma unroll
                for (int off = 16; off; off >>= 1)
                    lg[h] += __shfl_xor_sync(0xffffffffu, lg[h], off);
            if (lane == 0) {
#pragma unroll
                for (int h = 0; h < HEADS; h++) slog[e * HEADS + h] = lg[h];
            }
        }
        __syncthreads();
        // running-max update
        if (t < HEADS) {
            float mx = sm[t];
            for (int e = 0; e < cnt; e++) mx = fmaxf(mx, slog[e * HEADS + t]);
            sscale[t] = expf(sm[t] - mx);
            sm[t] = mx;
        }
        __syncthreads();
        for (int i = t; i < cnt * HEADS; i += 256)
            sw[i] = expf(slog[i] - sm[i & 7]);
        __syncthreads();
        if (t < HEADS) {
            float s = sden[t] * sscale[t];
            for (int e = 0; e < cnt; e++) s += sw[e * HEADS + t];
            sden[t] = s;
        }
        // rescale + accumulate (reads sw & sscale; sden not read here)
        acc *= sscale[head];
        for (int e = 0; e < cnt; e++)
            acc = fmaf(sw[e * HEADS + head], sxl[e][t], acc);
    }
    __syncthreads();

    float v = acc / (sden[head] + 1e-16f) + conv_b[t];
    v = (v - bn_rm[t]) * rsqrtf(bn_rv[t] + 1e-5f) * bn_g[t] + bn_b[t];
    v = v >= 0.f ? v : 0.01f * v;
    if (layer >= 1) v += g_h[(size_t)n * HID + t];
    g_h[(size_t)n * HID + t] = v;
}

// ------------------- output head: out = h2 @ W2 + b2 -------------------
__global__ void k_out(const float* __restrict__ W2, const float* __restrict__ b2,
                      float* __restrict__ out) {
    int n = (blockIdx.x * blockDim.x + threadIdx.x) >> 5;
    int lane = threadIdx.x & 31;
    if (n >= N_NODES) return;
    const float* hr = g_h2 + (size_t)n * 128;
    float a = 0.f;
#pragma unroll
    for (int j = 0; j < 4; j++) a += hr[j * 32 + lane] * W2[j * 32 + lane];
#pragma unroll
    for (int off = 16; off; off >>= 1) a += __shfl_xor_sync(0xffffffffu, a, off);
    if (lane == 0) out[n] = a + b2[0];
}

// ------------------- launcher -------------------
extern "C" void kernel_launch(void* const* d_in, const int* in_sizes, int n_in,
                              void* d_out, int out_size) {
    const float* x        = (const float*)d_in[0];
    const int*   ei       = (const int*)d_in[1];
    const float* eattr    = (const float*)d_in[2];
    const float* node_W   = (const float*)d_in[3];
    const float* node_b   = (const float*)d_in[4];
    const float* edge_W   = (const float*)d_in[5];
    const float* edge_b   = (const float*)d_in[6];
    const float* Wl       = (const float*)d_in[7];
    const float* bl       = (const float*)d_in[8];
    const float* Wr       = (const float*)d_in[9];
    const float* br       = (const float*)d_in[10];
    const float* We       = (const float*)d_in[11];
    const float* att      = (const float*)d_in[12];
    const float* conv_b   = (const float*)d_in[13];
    const float* Weu      = (const float*)d_in[14];
    const float* beu      = (const float*)d_in[15];
    const float* bn_g     = (const float*)d_in[16];
    const float* bn_b     = (const float*)d_in[17];
    const float* bn_rm    = (const float*)d_in[18];
    const float* bn_rv    = (const float*)d_in[19];
    const float* out_W1   = (const float*)d_in[20];
    const float* out_b1   = (const float*)d_in[21];
    const float* out_W2   = (const float*)d_in[22];
    const float* out_b2   = (const float*)d_in[23];
    float* out = (float*)d_out;

    const int* src = ei;
    const int* dst = ei + E_EDGES;

    float *hPtr, *xlPtr, *xrPtr, *h2Ptr, *Pp, *qp;
    cudaGetSymbolAddress((void**)&hPtr, g_h);
    cudaGetSymbolAddress((void**)&xlPtr, g_xl);
    cudaGetSymbolAddress((void**)&xrPtr, g_xr);
    cudaGetSymbolAddress((void**)&h2Ptr, g_h2);
    cudaGetSymbolAddress((void**)&Pp, g_P);
    cudaGetSymbolAddress((void**)&qp, g_q);

    // CSR build
    k_zero_fill<<<cdiv(N_NODES, 256), 256>>>();
    k_count<<<cdiv(E_EDGES, 256), 256>>>(dst);
    k_scan<<<1, 1024>>>();
    k_scatter<<<cdiv(E_EDGES, 256), 256>>>(src, dst);
    k_permattr<<<cdiv(E_EDGES * EDGE_IN, 256), 256>>>(eattr);

    // node input projection
    k_hinit<<<N_NODES, HID>>>(x, node_W, node_b);

    // fp32-exact composition of the linear edge chain
    k_initM<<<1, HID>>>(edge_W, edge_b);
    for (int i = 0; i < L_LAYERS; i++)
        k_compose<<<1, HID>>>(We + (size_t)i * HID * HID, Weu + (size_t)i * HID * HID,
                              beu + i * HID, i, i & 1, i < L_LAYERS - 1 ? 1 : 0);

    for (int i = 0; i < L_LAYERS; i++) {
        const float* Wl_i = Wl + (size_t)i * HID * HID;
        const float* Wr_i = Wr + (size_t)i * HID * HID;

        dim3 gN(cdiv(HID, 128), cdiv(N_NODES, 128));

        k_mma<<<gN, 256>>>(hPtr, Wl_i, bl + i * HID, xlPtr, N_NODES, HID, HID, 0);
        k_mma<<<gN, 256>>>(hPtr, Wr_i, br + i * HID, xrPtr, N_NODES, HID, HID, 0);

        k_fused<<<N_NODES, 256>>>(Pp + (size_t)i * EDGE_IN * HID, qp + (size_t)i * HID,
                                  att + (size_t)i * HEADS * OUTC,
                                  conv_b + i * HID, bn_g + i * HID, bn_b + i * HID,
                                  bn_rm + i * HID, bn_rv + i * HID, i);
    }

    // output MLP
    dim3 gO(1, cdiv(N_NODES, 128));
    k_mma<<<gO, 256>>>(hPtr, out_W1, out_b1, h2Ptr, N_NODES, HID / 2, HID, 1);
    k_out<<<cdiv(N_NODES * 32, 256), 256>>>(out_W2, out_b2, out);
}

// round 8
// speedup vs baseline: 1.9211x; 1.9211x over previous
#include <cuda_runtime.h>
#include <cstdint>

#define N_NODES 30000
#define E_EDGES 480000
#define HID 256
#define HEADS 8
#define OUTC 32
#define L_LAYERS 6
#define NODE_IN 13
#define EDGE_IN 10

// ------------------- static device scratch -------------------
__device__ float g_h[N_NODES * HID];
__device__ float g_xl[N_NODES * HID];
__device__ float g_xr[N_NODES * HID];
__device__ float g_attrS[E_EDGES * EDGE_IN];   // permuted edge_attr (sorted edge order)
__device__ float g_logits[E_EDGES * HEADS];
__device__ float g_h2[N_NODES * (HID / 2)];
__device__ float g_M[2][EDGE_IN * HID];        // composed attr->ea maps (ping-pong)
__device__ float g_cc[2][HID];
__device__ float g_P[L_LAYERS][EDGE_IN * HID]; // composed attr->ep maps
__device__ float g_q[L_LAYERS][HID];
__device__ int g_rowptr[N_NODES + 1];
__device__ int g_fill[N_NODES];
__device__ int g_perm[E_EDGES];
__device__ int g_src[E_EDGES];

static inline int cdiv(int a, int b) { return (a + b - 1) / b; }

// ------------------- CSR build -------------------
__global__ void k_zero_fill() {
    int i = blockIdx.x * blockDim.x + threadIdx.x;
    if (i < N_NODES) g_fill[i] = 0;
}

__global__ void k_count(const int* __restrict__ dst) {
    int e = blockIdx.x * blockDim.x + threadIdx.x;
    if (e < E_EDGES) atomicAdd(&g_fill[dst[e]], 1);
}

__global__ void k_scan() {  // single block, 1024 threads
    __shared__ int sh[1024];
    __shared__ int carry;
    int t = threadIdx.x;
    if (t == 0) carry = 0;
    __syncthreads();
    for (int base = 0; base < N_NODES; base += 1024) {
        int cbase = carry;
        int i = base + t;
        int v = (i < N_NODES) ? g_fill[i] : 0;
        sh[t] = v;
        __syncthreads();
        for (int off = 1; off < 1024; off <<= 1) {
            int tmp = (t >= off) ? sh[t - off] : 0;
            __syncthreads();
            sh[t] += tmp;
            __syncthreads();
        }
        if (i < N_NODES) {
            int ex = cbase + sh[t] - v;
            g_rowptr[i] = ex;
            g_fill[i] = ex;
        }
        __syncthreads();
        if (t == 0) carry = cbase + sh[1023];
        __syncthreads();
    }
    if (t == 0) g_rowptr[N_NODES] = carry;
}

__global__ void k_scatter(const int* __restrict__ src, const int* __restrict__ dst) {
    int e = blockIdx.x * blockDim.x + threadIdx.x;
    if (e < E_EDGES) {
        int d = dst[e];
        int pos = atomicAdd(&g_fill[d], 1);
        g_perm[pos] = e;
        g_src[pos] = src[e];
    }
}

__global__ void k_permattr(const float* __restrict__ eattr) {
    int i = blockIdx.x * blockDim.x + threadIdx.x;
    if (i < E_EDGES * EDGE_IN) {
        int e = i / EDGE_IN, j = i - e * EDGE_IN;
        g_attrS[i] = eattr[(size_t)g_perm[e] * EDGE_IN + j];
    }
}

// ------------------- node input projection -------------------
__global__ void k_hinit(const float* __restrict__ x, const float* __restrict__ W,
                        const float* __restrict__ b) {
    int n = blockIdx.x;
    int c = threadIdx.x;
    __shared__ float xr_[NODE_IN];
    if (c < NODE_IN) xr_[c] = x[n * NODE_IN + c];
    __syncthreads();
    float a = b[c];
#pragma unroll
    for (int k = 0; k < NODE_IN; k++) a += xr_[k] * W[k * HID + c];
    g_h[(size_t)n * HID + c] = a;
}

// ------------------- linear edge-chain composition (fp32 exact) -------------------
__global__ void k_initM(const float* __restrict__ edge_W, const float* __restrict__ edge_b) {
    int c = threadIdx.x;
#pragma unroll
    for (int r = 0; r < EDGE_IN; r++) g_M[0][r * HID + c] = edge_W[r * HID + c];
    g_cc[0][c] = edge_b[c];
}

// computes P_i = M@We, q_i = c@We; and (if doNext) M' = M@Weu, c' = c@Weu + beu
__global__ void k_compose(const float* __restrict__ We, const float* __restrict__ Weu,
                          const float* __restrict__ beu, int layer, int cur, int doNext) {
    int c = threadIdx.x;  // 256
    __shared__ float sM[EDGE_IN * HID];
    __shared__ float sc[HID];
    for (int t = c; t < EDGE_IN * HID; t += HID) sM[t] = g_M[cur][t];
    sc[c] = g_cc[cur][c];
    __syncthreads();
    float accP[EDGE_IN], accM[EDGE_IN];
    float accq = 0.f, accc = 0.f;
#pragma unroll
    for (int r = 0; r < EDGE_IN; r++) { accP[r] = 0.f; accM[r] = 0.f; }
    for (int k = 0; k < HID; k++) {
        float we = We[k * HID + c];
        float wu = doNext ? Weu[k * HID + c] : 0.f;
        float ck = sc[k];
        accq += ck * we;
        accc += ck * wu;
#pragma unroll
        for (int r = 0; r < EDGE_IN; r++) {
            float m = sM[r * HID + k];
            accP[r] += m * we;
            accM[r] += m * wu;
        }
    }
#pragma unroll
    for (int r = 0; r < EDGE_IN; r++) g_P[layer][r * HID + c] = accP[r];
    g_q[layer][c] = accq;
    if (doNext) {
#pragma unroll
        for (int r = 0; r < EDGE_IN; r++) g_M[1 - cur][r * HID + c] = accM[r];
        g_cc[1 - cur][c] = accc + beu[c];
    }
}

// ------------------- tf32 helpers -------------------
__device__ __forceinline__ uint32_t f2tf32(float x) {
    uint32_t r;
    asm("cvt.rna.tf32.f32 %0, %1;" : "=r"(r) : "f"(x));
    return r;
}

__device__ __forceinline__ void mma_tf32(float& c0, float& c1, float& c2, float& c3,
                                         uint32_t a0, uint32_t a1, uint32_t a2, uint32_t a3,
                                         uint32_t b0, uint32_t b1) {
    asm volatile(
        "mma.sync.aligned.m16n8k8.row.col.f32.tf32.tf32.f32 "
        "{%0,%1,%2,%3},{%4,%5,%6,%7},{%8,%9},{%0,%1,%2,%3};\n"
        : "+f"(c0), "+f"(c1), "+f"(c2), "+f"(c3)
        : "r"(a0), "r"(a1), "r"(a2), "r"(a3), "r"(b0), "r"(b1));
}

// ------------------- tensor-core GEMM, 128x128x32 tiles -------------------
__global__ __launch_bounds__(256, 2) void k_mma(const float* __restrict__ A,
                                                const float* __restrict__ B,
                                                const float* __restrict__ bias,
                                                float* __restrict__ C,
                                                int M, int N, int K, int act) {
    __shared__ uint32_t As[128][36];
    __shared__ uint32_t Bs[32][136];

    const int tid = threadIdx.x;
    const int lane = tid & 31;
    const int warp = tid >> 5;
    const int g = lane >> 2;
    const int t4 = lane & 3;
    const int wm = warp >> 1;
    const int wn = warp & 1;
    const int row0 = blockIdx.y * 128;
    const int col0 = blockIdx.x * 128;

    float acc[2][8][4];
#pragma unroll
    for (int mi = 0; mi < 2; mi++)
#pragma unroll
        for (int ni = 0; ni < 8; ni++)
#pragma unroll
            for (int c = 0; c < 4; c++) acc[mi][ni][c] = 0.f;

    for (int kt = 0; kt < K; kt += 32) {
#pragma unroll
        for (int v = 0; v < 4; v++) {
            int f = tid + v * 256;
            int row = f >> 3;
            int c4 = f & 7;
            int r = row0 + row;
            float4 av = make_float4(0.f, 0.f, 0.f, 0.f);
            if (r < M) av = *(const float4*)(A + (size_t)r * K + kt + c4 * 4);
            uint4 u;
            u.x = f2tf32(av.x); u.y = f2tf32(av.y); u.z = f2tf32(av.z); u.w = f2tf32(av.w);
            *(uint4*)&As[row][c4 * 4] = u;
        }
#pragma unroll
        for (int v = 0; v < 4; v++) {
            int f = tid + v * 256;
            int row = f >> 5;
            int c4 = f & 31;
            float4 bv = *(const float4*)(B + (size_t)(kt + row) * N + col0 + c4 * 4);
            uint4 u;
            u.x = f2tf32(bv.x); u.y = f2tf32(bv.y); u.z = f2tf32(bv.z); u.w = f2tf32(bv.w);
            *(uint4*)&Bs[row][c4 * 4] = u;
        }
        __syncthreads();

#pragma unroll
        for (int kk = 0; kk < 4; kk++) {
            int k0 = kk * 8;
            uint32_t a[2][4];
#pragma unroll
            for (int mi = 0; mi < 2; mi++) {
                int mrow = wm * 32 + mi * 16;
                a[mi][0] = As[mrow + g][k0 + t4];
                a[mi][1] = As[mrow + 8 + g][k0 + t4];
                a[mi][2] = As[mrow + g][k0 + t4 + 4];
                a[mi][3] = As[mrow + 8 + g][k0 + t4 + 4];
            }
            uint32_t b[8][2];
#pragma unroll
            for (int ni = 0; ni < 8; ni++) {
                int ncol = wn * 64 + ni * 8;
                b[ni][0] = Bs[k0 + t4][ncol + g];
                b[ni][1] = Bs[k0 + t4 + 4][ncol + g];
            }
#pragma unroll
            for (int mi = 0; mi < 2; mi++)
#pragma unroll
                for (int ni = 0; ni < 8; ni++)
                    mma_tf32(acc[mi][ni][0], acc[mi][ni][1], acc[mi][ni][2], acc[mi][ni][3],
                             a[mi][0], a[mi][1], a[mi][2], a[mi][3], b[ni][0], b[ni][1]);
        }
        __syncthreads();
    }

#pragma unroll
    for (int mi = 0; mi < 2; mi++) {
#pragma unroll
        for (int j = 0; j < 2; j++) {
            int r = row0 + wm * 32 + mi * 16 + j * 8 + g;
            if (r >= M) continue;
#pragma unroll
            for (int ni = 0; ni < 8; ni++) {
                int c = col0 + wn * 64 + ni * 8 + 2 * t4;
                float v0 = acc[mi][ni][j * 2 + 0];
                float v1 = acc[mi][ni][j * 2 + 1];
                if (bias) { v0 += bias[c]; v1 += bias[c + 1]; }
                if (act == 1) {
                    v0 = v0 >= 0.f ? v0 : 0.01f * v0;
                    v1 = v1 >= 0.f ? v1 : 0.01f * v1;
                }
                *(float2*)(C + (size_t)r * N + c) = make_float2(v0, v1);
            }
        }
    }
}

// ------------------- fused edge logits (ep composed on the fly) -------------------
// warp per edge (grid-stride); lane owns channels c = lane*8 .. lane*8+7 (head = lane/4)
__global__ __launch_bounds__(256, 2) void k_logits(const float* __restrict__ P,
                                                   const float* __restrict__ q,
                                                   const float* __restrict__ att) {
    const int lane = threadIdx.x & 31;
    const int wid = threadIdx.x >> 5;
    const int wpb = blockDim.x >> 5;
    const int c0 = lane * 8;

    // per-lane constants (my 8 channels)
    float Pr[EDGE_IN][8], qr[8], ar[8];
    {
        float4 qa = *(const float4*)(q + c0);
        float4 qb = *(const float4*)(q + c0 + 4);
        qr[0] = qa.x; qr[1] = qa.y; qr[2] = qa.z; qr[3] = qa.w;
        qr[4] = qb.x; qr[5] = qb.y; qr[6] = qb.z; qr[7] = qb.w;
        float4 aa = *(const float4*)(att + c0);
        float4 ab = *(const float4*)(att + c0 + 4);
        ar[0] = aa.x; ar[1] = aa.y; ar[2] = aa.z; ar[3] = aa.w;
        ar[4] = ab.x; ar[5] = ab.y; ar[6] = ab.z; ar[7] = ab.w;
#pragma unroll
        for (int k = 0; k < EDGE_IN; k++) {
            float4 pa = *(const float4*)(P + k * HID + c0);
            float4 pb = *(const float4*)(P + k * HID + c0 + 4);
            Pr[k][0] = pa.x; Pr[k][1] = pa.y; Pr[k][2] = pa.z; Pr[k][3] = pa.w;
            Pr[k][4] = pb.x; Pr[k][5] = pb.y; Pr[k][6] = pb.z; Pr[k][7] = pb.w;
        }
    }

    for (int e = blockIdx.x * wpb + wid; e < E_EDGES; e += gridDim.x * wpb) {
        int s = g_src[e];
        const float* ap = g_attrS + (size_t)e * EDGE_IN;
        float attr[EDGE_IN];
#pragma unroll
        for (int k = 0; k < EDGE_IN; k++) attr[k] = __ldg(ap + k);

        float4 xla = *(const float4*)(g_xl + (size_t)s * HID + c0);
        float4 xlb = *(const float4*)(g_xl + (size_t)s * HID + c0 + 4);
        float xlv[8] = {xla.x, xla.y, xla.z, xla.w, xlb.x, xlb.y, xlb.z, xlb.w};

        int d = ((const int*)g_perm)[e];  // g_perm repurposed: holds dst after setup
        float4 xra = *(const float4*)(g_xr + (size_t)d * HID + c0);
        float4 xrb = *(const float4*)(g_xr + (size_t)d * HID + c0 + 4);
        float xrv[8] = {xra.x, xra.y, xra.z, xra.w, xrb.x, xrb.y, xrb.z, xrb.w};

        float part = 0.f;
#pragma unroll
        for (int j = 0; j < 8; j++) {
            float ep = qr[j];
#pragma unroll
            for (int k = 0; k < EDGE_IN; k++) ep = fmaf(attr[k], Pr[k][j], ep);
            float m = xlv[j] + xrv[j] + ep;
            m = m >= 0.f ? m : 0.2f * m;
            part = fmaf(m, ar[j], part);
        }
        part += __shfl_xor_sync(0xffffffffu, part, 1);
        part += __shfl_xor_sync(0xffffffffu, part, 2);
        if ((lane & 3) == 0)
            g_logits[(size_t)e * HEADS + (lane >> 2)] = part;
    }
}

// after k_permattr, overwrite g_perm with sorted dst (edge -> dst node)
__global__ void k_filldst() {
    int n = blockIdx.x * blockDim.x + threadIdx.x;
    if (n < N_NODES) {
        int s0 = g_rowptr[n], s1 = g_rowptr[n + 1];
        for (int i = s0; i < s1; i++) g_perm[i] = n;
    }
}

// ------------------- warp-per-node softmax + aggregation + BN + residual ----------
__global__ __launch_bounds__(256) void k_agg2(const float* __restrict__ conv_b,
                                              const float* __restrict__ bn_g,
                                              const float* __restrict__ bn_b,
                                              const float* __restrict__ bn_rm,
                                              const float* __restrict__ bn_rv,
                                              int layer) {
    int n = (blockIdx.x * blockDim.x + threadIdx.x) >> 5;
    int lane = threadIdx.x & 31;
    if (n >= N_NODES) return;
    const int hd = lane >> 2;       // head of my channels
    const int c0 = lane * 8;
    const int s0 = g_rowptr[n], s1 = g_rowptr[n + 1];

    // pass 1: per-head max (broadcast 32B loads, L1-hot afterwards)
    float mx = -1e30f;
    for (int i = s0; i < s1; i++)
        mx = fmaxf(mx, __ldg(g_logits + (size_t)i * HEADS + hd));
    // pass 2: denominator
    float den = 0.f;
    for (int i = s0; i < s1; i++)
        den += expf(__ldg(g_logits + (size_t)i * HEADS + hd) - mx);
    den += 1e-16f;
    // pass 3: weighted aggregation
    float acc[8];
#pragma unroll
    for (int j = 0; j < 8; j++) acc[j] = 0.f;
    for (int i = s0; i < s1; i++) {
        float w = expf(__ldg(g_logits + (size_t)i * HEADS + hd) - mx);
        int s = g_src[i];
        float4 a = *(const float4*)(g_xl + (size_t)s * HID + c0);
        float4 b = *(const float4*)(g_xl + (size_t)s * HID + c0 + 4);
        acc[0] = fmaf(w, a.x, acc[0]); acc[1] = fmaf(w, a.y, acc[1]);
        acc[2] = fmaf(w, a.z, acc[2]); acc[3] = fmaf(w, a.w, acc[3]);
        acc[4] = fmaf(w, b.x, acc[4]); acc[5] = fmaf(w, b.y, acc[5]);
        acc[6] = fmaf(w, b.z, acc[6]); acc[7] = fmaf(w, b.w, acc[7]);
    }

    // epilogue: conv_b + BN + leaky + residual
    float cb[8], gg[8], bb[8], rm[8], rv[8], hres[8];
    {
        float4 t0, t1;
        t0 = *(const float4*)(conv_b + c0); t1 = *(const float4*)(conv_b + c0 + 4);
        cb[0]=t0.x; cb[1]=t0.y; cb[2]=t0.z; cb[3]=t0.w; cb[4]=t1.x; cb[5]=t1.y; cb[6]=t1.z; cb[7]=t1.w;
        t0 = *(const float4*)(bn_g + c0); t1 = *(const float4*)(bn_g + c0 + 4);
        gg[0]=t0.x; gg[1]=t0.y; gg[2]=t0.z; gg[3]=t0.w; gg[4]=t1.x; gg[5]=t1.y; gg[6]=t1.z; gg[7]=t1.w;
        t0 = *(const float4*)(bn_b + c0); t1 = *(const float4*)(bn_b + c0 + 4);
        bb[0]=t0.x; bb[1]=t0.y; bb[2]=t0.z; bb[3]=t0.w; bb[4]=t1.x; bb[5]=t1.y; bb[6]=t1.z; bb[7]=t1.w;
        t0 = *(const float4*)(bn_rm + c0); t1 = *(const float4*)(bn_rm + c0 + 4);
        rm[0]=t0.x; rm[1]=t0.y; rm[2]=t0.z; rm[3]=t0.w; rm[4]=t1.x; rm[5]=t1.y; rm[6]=t1.z; rm[7]=t1.w;
        t0 = *(const float4*)(bn_rv + c0); t1 = *(const float4*)(bn_rv + c0 + 4);
        rv[0]=t0.x; rv[1]=t0.y; rv[2]=t0.z; rv[3]=t0.w; rv[4]=t1.x; rv[5]=t1.y; rv[6]=t1.z; rv[7]=t1.w;
        if (layer >= 1) {
            t0 = *(const float4*)(g_h + (size_t)n * HID + c0);
            t1 = *(const float4*)(g_h + (size_t)n * HID + c0 + 4);
            hres[0]=t0.x; hres[1]=t0.y; hres[2]=t0.z; hres[3]=t0.w;
            hres[4]=t1.x; hres[5]=t1.y; hres[6]=t1.z; hres[7]=t1.w;
        }
    }
    float outv[8];
#pragma unroll
    for (int j = 0; j < 8; j++) {
        float v = acc[j] / den + cb[j];
        v = (v - rm[j]) * rsqrtf(rv[j] + 1e-5f) * gg[j] + bb[j];
        v = v >= 0.f ? v : 0.01f * v;
        if (layer >= 1) v += hres[j];
        outv[j] = v;
    }
    *(float4*)(g_h + (size_t)n * HID + c0) = make_float4(outv[0], outv[1], outv[2], outv[3]);
    *(float4*)(g_h + (size_t)n * HID + c0 + 4) = make_float4(outv[4], outv[5], outv[6], outv[7]);
}

// ------------------- output head: out = h2 @ W2 + b2 -------------------
__global__ void k_out(const float* __restrict__ W2, const float* __restrict__ b2,
                      float* __restrict__ out) {
    int n = (blockIdx.x * blockDim.x + threadIdx.x) >> 5;
    int lane = threadIdx.x & 31;
    if (n >= N_NODES) return;
    const float* hr = g_h2 + (size_t)n * 128;
    float a = 0.f;
#pragma unroll
    for (int j = 0; j < 4; j++) a += hr[j * 32 + lane] * W2[j * 32 + lane];
#pragma unroll
    for (int off = 16; off; off >>= 1) a += __shfl_xor_sync(0xffffffffu, a, off);
    if (lane == 0) out[n] = a + b2[0];
}

// ------------------- launcher -------------------
extern "C" void kernel_launch(void* const* d_in, const int* in_sizes, int n_in,
                              void* d_out, int out_size) {
    const float* x        = (const float*)d_in[0];
    const int*   ei       = (const int*)d_in[1];
    const float* eattr    = (const float*)d_in[2];
    const float* node_W   = (const float*)d_in[3];
    const float* node_b   = (const float*)d_in[4];
    const float* edge_W   = (const float*)d_in[5];
    const float* edge_b   = (const float*)d_in[6];
    const float* Wl       = (const float*)d_in[7];
    const float* bl       = (const float*)d_in[8];
    const float* Wr       = (const float*)d_in[9];
    const float* br       = (const float*)d_in[10];
    const float* We       = (const float*)d_in[11];
    const float* att      = (const float*)d_in[12];
    const float* conv_b   = (const float*)d_in[13];
    const float* Weu      = (const float*)d_in[14];
    const float* beu      = (const float*)d_in[15];
    const float* bn_g     = (const float*)d_in[16];
    const float* bn_b     = (const float*)d_in[17];
    const float* bn_rm    = (const float*)d_in[18];
    const float* bn_rv    = (const float*)d_in[19];
    const float* out_W1   = (const float*)d_in[20];
    const float* out_b1   = (const float*)d_in[21];
    const float* out_W2   = (const float*)d_in[22];
    const float* out_b2   = (const float*)d_in[23];
    float* out = (float*)d_out;

    const int* src = ei;
    const int* dst = ei + E_EDGES;

    float *hPtr, *h2Ptr, *xlPtr, *xrPtr, *Pp, *qp;
    cudaGetSymbolAddress((void**)&hPtr, g_h);
    cudaGetSymbolAddress((void**)&xlPtr, g_xl);
    cudaGetSymbolAddress((void**)&xrPtr, g_xr);
    cudaGetSymbolAddress((void**)&h2Ptr, g_h2);
    cudaGetSymbolAddress((void**)&Pp, g_P);
    cudaGetSymbolAddress((void**)&qp, g_q);

    // CSR build
    k_zero_fill<<<cdiv(N_NODES, 256), 256>>>();
    k_count<<<cdiv(E_EDGES, 256), 256>>>(dst);
    k_scan<<<1, 1024>>>();
    k_scatter<<<cdiv(E_EDGES, 256), 256>>>(src, dst);
    k_permattr<<<cdiv(E_EDGES * EDGE_IN, 256), 256>>>(eattr);
    k_filldst<<<cdiv(N_NODES, 256), 256>>>();  // g_perm now holds per-edge dst

    // node input projection
    k_hinit<<<N_NODES, HID>>>(x, node_W, node_b);

    // fp32-exact composition of the linear edge chain
    k_initM<<<1, HID>>>(edge_W, edge_b);
    for (int i = 0; i < L_LAYERS; i++)
        k_compose<<<1, HID>>>(We + (size_t)i * HID * HID, Weu + (size_t)i * HID * HID,
                              beu + i * HID, i, i & 1, i < L_LAYERS - 1 ? 1 : 0);

    for (int i = 0; i < L_LAYERS; i++) {
        const float* Wl_i = Wl + (size_t)i * HID * HID;
        const float* Wr_i = Wr + (size_t)i * HID * HID;

        dim3 gN(cdiv(HID, 128), cdiv(N_NODES, 128));

        k_mma<<<gN, 256>>>(hPtr, Wl_i, bl + i * HID, xlPtr, N_NODES, HID, HID, 0);
        k_mma<<<gN, 256>>>(hPtr, Wr_i, br + i * HID, xrPtr, N_NODES, HID, HID, 0);

        k_logits<<<2048, 256>>>(Pp + (size_t)i * EDGE_IN * HID, qp + (size_t)i * HID,
                                att + (size_t)i * HEADS * OUTC);
        k_agg2<<<cdiv(N_NODES * 32, 256), 256>>>(conv_b + i * HID, bn_g + i * HID,
                                                 bn_b + i * HID, bn_rm + i * HID,
                                                 bn_rv + i * HID, i);
    }

    // output MLP
    dim3 gO(1, cdiv(N_NODES, 128));
    k_mma<<<gO, 256>>>(hPtr, out_W1, out_b1, h2Ptr, N_NODES, HID / 2, HID, 1);
    k_out<<<cdiv(N_NODES * 32, 256), 256>>>(out_W2, out_b2, out);
}